// round 7
// baseline (speedup 1.0000x reference)
#include <cuda_runtime.h>
#include <cuda_bf16.h>

#define THREADS 256

// Reference dataflow (after dead-code elimination):
//   s_b   = relu(dot(inputs[b,:], W1) + b1)                  -- only 70 b's needed
//   x[b,c]= relu(s_b * W2[0,c] + b2[c])
// Branch3 (i=0..63): v = x[i*64, 1]; h = relu(v*W3a+b3a);
//   o[j] = relu(h*W3b[j]+b3b[j]), j=0..79
//   out[t*5120 + i*80 + j] = o[j]  for t=0..79   (tile by 80)
// Gap: out[409600..409663] = 0
// Branch4 (i=0..5): k=i*4096+1; row=k/6; c=64+k%6; v=x[row,c];
//   h = relu(v*W4a+b4a); out[409664 + i*513 + j] = relu(h*W4b[j]+b4b[j]), j=0..512

__global__ void hyper_pong_kernel(const float* __restrict__ inputs,
                                  const float* __restrict__ W1,
                                  const float* __restrict__ b1,
                                  const float* __restrict__ W2,
                                  const float* __restrict__ b2,
                                  const float* __restrict__ W3a,
                                  const float* __restrict__ b3a,
                                  const float* __restrict__ W3b,
                                  const float* __restrict__ b3b,
                                  const float* __restrict__ W4a,
                                  const float* __restrict__ b4a,
                                  const float* __restrict__ W4b,
                                  const float* __restrict__ b4b,
                                  float* __restrict__ out)
{
    const int blk = blockIdx.x;
    const int tid = threadIdx.x;

    if (blk == 70) {
        // the 64-element zero "bias" segment
        if (tid < 64) out[409600 + tid] = 0.0f;
        return;
    }

    // Which batch row + which W2 column does this block need?
    int row, col;
    if (blk < 64) {
        row = blk * 64;
        col = 1;
    } else {
        int k = (blk - 64) * 4096 + 1;
        row = k / 6;
        col = 64 + (k % 6);
    }

    // ---- dot(inputs[row], W1) over 6400 elements, float4-vectorized ----
    const float4* ip = reinterpret_cast<const float4*>(inputs + (size_t)row * 6400);
    const float4* wp = reinterpret_cast<const float4*>(W1);
    float acc = 0.0f;
    #pragma unroll 4
    for (int i = tid; i < 1600; i += THREADS) {
        float4 a = ip[i];
        float4 w = wp[i];
        acc += a.x * w.x + a.y * w.y + a.z * w.z + a.w * w.w;
    }

    // ---- block reduction ----
    __shared__ float sred[THREADS / 32];
    #pragma unroll
    for (int off = 16; off > 0; off >>= 1)
        acc += __shfl_down_sync(0xffffffffu, acc, off);
    if ((tid & 31) == 0) sred[tid >> 5] = acc;
    __syncthreads();

    __shared__ float h_sh;
    if (tid == 0) {
        float s = 0.0f;
        #pragma unroll
        for (int i = 0; i < THREADS / 32; i++) s += sred[i];
        s = fmaxf(s + b1[0], 0.0f);                         // layer 1 + relu
        float v = fmaxf(fmaf(s, W2[col], b2[col]), 0.0f);   // layer 2 + relu
        float h;
        if (blk < 64) h = fmaxf(fmaf(v, W3a[0], b3a[0]), 0.0f);
        else          h = fmaxf(fmaf(v, W4a[0], b4a[0]), 0.0f);
        h_sh = h;
    }
    __syncthreads();
    const float h = h_sh;

    if (blk < 64) {
        // Precompute the 80 output values once into shared (as 20 float4),
        // then fan out 80 tile replicas with STG.128.
        __shared__ float4 ovals4[20];
        if (tid < 80) {
            float v = fmaxf(fmaf(h, W3b[tid], b3b[tid]), 0.0f);
            reinterpret_cast<float*>(ovals4)[tid] = v;
        }
        __syncthreads();

        // out[t*5120 + blk*80 + j] for t=0..79, j=0..79 → 1600 float4 stores.
        // Both 5120 and 80 are multiples of 4, so all stores are 16B-aligned.
        float4* outv = reinterpret_cast<float4*>(out + blk * 80);
        for (int idx = tid; idx < 1600; idx += THREADS) {
            int t = idx / 20;          // tile replica
            int q = idx - t * 20;      // float4 index within the 80-value segment
            outv[t * 1280 + q] = ovals4[q];   // 1280 = 5120/4
        }
    } else {
        const int base = 409664 + (blk - 64) * 513;
        for (int j = tid; j < 513; j += THREADS)
            out[base + j] = fmaxf(fmaf(h, W4b[j], b4b[j]), 0.0f);
    }
}

extern "C" void kernel_launch(void* const* d_in, const int* in_sizes, int n_in,
                              void* d_out, int out_size)
{
    const float* inputs = (const float*)d_in[0];
    const float* W1     = (const float*)d_in[1];
    const float* b1     = (const float*)d_in[2];
    const float* W2     = (const float*)d_in[3];
    const float* b2     = (const float*)d_in[4];
    const float* W3a    = (const float*)d_in[5];
    const float* b3a    = (const float*)d_in[6];
    const float* W3b    = (const float*)d_in[7];
    const float* b3b    = (const float*)d_in[8];
    const float* W4a    = (const float*)d_in[9];
    const float* b4a    = (const float*)d_in[10];
    const float* W4b    = (const float*)d_in[11];
    const float* b4b    = (const float*)d_in[12];
    float* out = (float*)d_out;

    hyper_pong_kernel<<<71, THREADS>>>(inputs, W1, b1, W2, b2,
                                       W3a, b3a, W3b, b3b,
                                       W4a, b4a, W4b, b4b, out);
}

// round 8
// speedup vs baseline: 1.0290x; 1.0290x over previous
#include <cuda_runtime.h>
#include <cuda_bf16.h>

#define THREADS 1024

// Dead-code-eliminated dataflow (see prior rounds):
//   s   = relu(dot(inputs[row,:], W1) + b1)    -- only 70 rows matter
//   v   = relu(s * W2[col] + b2[col])
// Branch3 (blk=0..63): row=blk*64, col=1; h=relu(v*W3a+b3a);
//   o[j]=relu(h*W3b[j]+b3b[j]); out[t*5120+blk*80+j]=o[j] for t=0..79
// Gap: out[409600..409663]=0  (folded into blk 64)
// Branch4 (blk=64..69): k=(blk-64)*4096+1; row=k/6; col=64+k%6;
//   h=relu(v*W4a+b4a); out[409664+(blk-64)*513+j]=relu(h*W4b[j]+b4b[j])

__global__ __launch_bounds__(THREADS, 1)
void hyper_pong_kernel(const float* __restrict__ inputs,
                       const float* __restrict__ W1,
                       const float* __restrict__ b1,
                       const float* __restrict__ W2,
                       const float* __restrict__ b2,
                       const float* __restrict__ W3a,
                       const float* __restrict__ b3a,
                       const float* __restrict__ W3b,
                       const float* __restrict__ b3b,
                       const float* __restrict__ W4a,
                       const float* __restrict__ b4a,
                       const float* __restrict__ W4b,
                       const float* __restrict__ b4b,
                       float* __restrict__ out)
{
    const int blk = blockIdx.x;
    const int tid = threadIdx.x;

    // Which batch row + which W2 column does this block need?
    int row, col;
    if (blk < 64) {
        row = blk * 64;
        col = 1;
    } else {
        int k = (blk - 64) * 4096 + 1;
        row = k / 6;
        col = 64 + (k % 6);
        // fold the 64-element zero gap into block 64
        if (blk == 64 && tid < 64) out[409600 + tid] = 0.0f;
    }

    // ---- dot(inputs[row], W1): 1600 float4 pairs, all loads issued up front ----
    const float4* ip = reinterpret_cast<const float4*>(inputs + (size_t)row * 6400);
    const float4* wp = reinterpret_cast<const float4*>(W1);

    // 1600 = 1024 + 576: every thread handles i = tid; threads < 576 also i = tid+1024.
    float4 a0 = ip[tid];
    float4 w0 = wp[tid];
    float4 a1, w1;
    const bool two = (tid < 576);
    if (two) {
        a1 = ip[tid + 1024];
        w1 = wp[tid + 1024];
    }
    float acc = a0.x * w0.x + a0.y * w0.y + a0.z * w0.z + a0.w * w0.w;
    if (two)
        acc += a1.x * w1.x + a1.y * w1.y + a1.z * w1.z + a1.w * w1.w;

    // ---- block reduction: 32 warps -> shfl tree -> warp-0 final shfl ----
    __shared__ float sred[32];
    #pragma unroll
    for (int off = 16; off > 0; off >>= 1)
        acc += __shfl_down_sync(0xffffffffu, acc, off);
    if ((tid & 31) == 0) sred[tid >> 5] = acc;
    __syncthreads();

    __shared__ float h_sh;
    if (tid < 32) {
        float s = sred[tid];
        #pragma unroll
        for (int off = 16; off > 0; off >>= 1)
            s += __shfl_down_sync(0xffffffffu, s, off);
        if (tid == 0) {
            s = fmaxf(s + b1[0], 0.0f);                         // layer 1 + relu
            float v = fmaxf(fmaf(s, W2[col], b2[col]), 0.0f);   // layer 2 + relu
            float h;
            if (blk < 64) h = fmaxf(fmaf(v, W3a[0], b3a[0]), 0.0f);
            else          h = fmaxf(fmaf(v, W4a[0], b4a[0]), 0.0f);
            h_sh = h;
        }
    }
    __syncthreads();
    const float h = h_sh;

    if (blk < 64) {
        // Precompute the 80 outputs once into shared (as 20 float4),
        // then fan out 80 tile replicas with STG.128.
        __shared__ float4 ovals4[20];
        if (tid < 80) {
            float v = fmaxf(fmaf(h, W3b[tid], b3b[tid]), 0.0f);
            reinterpret_cast<float*>(ovals4)[tid] = v;
        }
        __syncthreads();

        // out[t*5120 + blk*80 + 4q], t=0..79, q=0..19 -> 1600 float4 stores.
        float4* outv = reinterpret_cast<float4*>(out + blk * 80);
        {
            int idx = tid;                 // 0..1023
            int t = idx / 20, q = idx - t * 20;
            outv[t * 1280 + q] = ovals4[q];          // 1280 = 5120/4
        }
        if (tid < 576) {
            int idx = tid + 1024;          // 1024..1599
            int t = idx / 20, q = idx - t * 20;
            outv[t * 1280 + q] = ovals4[q];
        }
    } else {
        const int base = 409664 + (blk - 64) * 513;
        if (tid < 513)
            out[base + tid] = fmaxf(fmaf(h, W4b[tid], b4b[tid]), 0.0f);
    }
}

extern "C" void kernel_launch(void* const* d_in, const int* in_sizes, int n_in,
                              void* d_out, int out_size)
{
    const float* inputs = (const float*)d_in[0];
    const float* W1     = (const float*)d_in[1];
    const float* b1     = (const float*)d_in[2];
    const float* W2     = (const float*)d_in[3];
    const float* b2     = (const float*)d_in[4];
    const float* W3a    = (const float*)d_in[5];
    const float* b3a    = (const float*)d_in[6];
    const float* W3b    = (const float*)d_in[7];
    const float* b3b    = (const float*)d_in[8];
    const float* W4a    = (const float*)d_in[9];
    const float* b4a    = (const float*)d_in[10];
    const float* W4b    = (const float*)d_in[11];
    const float* b4b    = (const float*)d_in[12];
    float* out = (float*)d_out;

    hyper_pong_kernel<<<70, THREADS>>>(inputs, W1, b1, W2, b2,
                                       W3a, b3a, W3b, b3b,
                                       W4a, b4a, W4b, b4b, out);
}